// round 9
// baseline (speedup 1.0000x reference)
#include <cuda_runtime.h>
#include <cuda_fp16.h>
#include <cstdint>

// Problem constants
#define B_DIM 2
#define T_DIM 1024
#define H_DIM 32
#define P_DIM 64
#define N_DIM 128
#define BH (B_DIM * H_DIM)
#define Y_SIZE (B_DIM * T_DIM * H_DIM * P_DIM)
#define FS_SIZE (BH * P_DIM * N_DIM)
#define NSPLIT 8

__device__ float g_Acs[BH * T_DIM];
__device__ float g_part[NSPLIT * FS_SIZE];
// Preconverted fp16 tensors
__device__ __align__(16) __half g_Bh[BH * T_DIM * N_DIM];   // [bh][t][n]  16MB
__device__ __align__(16) __half g_Ch[BH * T_DIM * N_DIM];   // [bh][t][n]  16MB
__device__ __align__(16) __half g_Xt[BH * P_DIM * T_DIM];   // [bh][p][t]   8MB

// ---------------- helpers ----------------
__device__ __forceinline__ uint32_t smem_u32(const void* p) {
    uint32_t a;
    asm("{ .reg .u64 t; cvta.to.shared.u64 t, %1; cvt.u32.u64 %0, t; }" : "=r"(a) : "l"(p));
    return a;
}
__device__ __forceinline__ void ldsm4(uint32_t& r0, uint32_t& r1, uint32_t& r2, uint32_t& r3, uint32_t addr) {
    asm volatile("ldmatrix.sync.aligned.m8n8.x4.shared.b16 {%0,%1,%2,%3}, [%4];"
                 : "=r"(r0), "=r"(r1), "=r"(r2), "=r"(r3) : "r"(addr));
}
__device__ __forceinline__ void mma16816(float* d, uint32_t a0, uint32_t a1, uint32_t a2, uint32_t a3,
                                         uint32_t b0, uint32_t b1) {
    asm volatile("mma.sync.aligned.m16n8k16.row.col.f32.f16.f16.f32 "
                 "{%0,%1,%2,%3}, {%4,%5,%6,%7}, {%8,%9}, {%0,%1,%2,%3};"
                 : "+f"(d[0]), "+f"(d[1]), "+f"(d[2]), "+f"(d[3])
                 : "r"(a0), "r"(a1), "r"(a2), "r"(a3), "r"(b0), "r"(b1));
}
__device__ __forceinline__ uint32_t pack_h2(float x, float y) {
    uint32_t r;
    asm("cvt.rn.f16x2.f32 %0, %1, %2;" : "=r"(r) : "f"(y), "f"(x));
    return r;
}
#define CP_ASYNC16(dst, src) \
    asm volatile("cp.async.cg.shared.global [%0], [%1], 16;" :: "r"(dst), "l"(src))
#define CP_COMMIT()  asm volatile("cp.async.commit_group;" ::: "memory")
#define CP_WAIT2()   asm volatile("cp.async.wait_group 2;" ::: "memory")

// SMEM layout. Pitches keep ldmatrix rows in distinct 16B groups.
#define PCH 272
#define PXH 144
#define O_ECOL 0                              // 4 x 64 floats
#define O_C    1024                           // 128 * PCH = 34816
#define O_B    (O_C + 128 * PCH)              // 35840 ; 4 bufs x 17408
#define O_X    (O_B + 4 * 17408)              // 105472; 4 bufs x 9216
#define SMEM_BYTES (O_X + 4 * 9216)           // 142336

#define THREADS 512

// ---------------------------------------------------------------------------
__global__ void __launch_bounds__(1024) acs_kernel(const float* __restrict__ A) {
    int bh = blockIdx.x;
    int b = bh >> 5, h = bh & 31;
    __shared__ float buf[2][T_DIM];
    int t = threadIdx.x;
    buf[0][t] = A[(size_t)(b * T_DIM + t) * H_DIM + h];
    __syncthreads();
    int src = 0;
    for (int off = 1; off < T_DIM; off <<= 1) {
        float v = buf[src][t];
        if (t >= off) v += buf[src][t - off];
        buf[src ^ 1][t] = v;
        src ^= 1;
        __syncthreads();
    }
    g_Acs[bh * T_DIM + t] = buf[src][t];
}

// ---------------------------------------------------------------------------
// Preconvert B and C: [b,t,h,n] fp32 -> [bh][t][n] fp16
// ---------------------------------------------------------------------------
__global__ void __launch_bounds__(256) conv_bc_kernel(const float* __restrict__ Bg,
                                                      const float* __restrict__ Cg) {
    const float* src = blockIdx.y ? Cg : Bg;
    __half* dst = blockIdx.y ? g_Ch : g_Bh;
    int lin = blockIdx.x * 256 + threadIdx.x;      // 2^21 threads
    int q = lin & 31;
    int h = (lin >> 5) & 31;
    int t = (lin >> 10) & 1023;
    int b = lin >> 20;
    float4 v = *(const float4*)(src + ((size_t)((b * 1024 + t) * 32 + h)) * 128 + q * 4);
    uint2* o = (uint2*)(dst + ((size_t)((b * 32 + h) * 1024 + t)) * 128 + q * 4);
    *o = make_uint2(pack_h2(v.x, v.y), pack_h2(v.z, v.w));
}

// ---------------------------------------------------------------------------
// Preconvert + transpose X: [b,t,h,p] fp32 -> [bh][p][t] fp16
// ---------------------------------------------------------------------------
__global__ void __launch_bounds__(256) conv_x_kernel(const float* __restrict__ xg) {
    int tb = blockIdx.x;       // 16 t-chunks of 64
    int bh = blockIdx.y;
    int b = bh >> 5, h = bh & 31;
    __shared__ __half st[64 * 68];
    int u = threadIdx.x;
    int t0 = tb * 64;
#pragma unroll
    for (int k = 0; k < 4; ++k) {
        int lin = u + k * 256;
        int i = lin >> 4, fq = lin & 15;
        float4 v = *(const float4*)(xg + ((size_t)((b * 1024 + t0 + i) * 32 + h)) * 64 + fq * 4);
        st[i * 68 + fq * 4 + 0] = __float2half_rn(v.x);
        st[i * 68 + fq * 4 + 1] = __float2half_rn(v.y);
        st[i * 68 + fq * 4 + 2] = __float2half_rn(v.z);
        st[i * 68 + fq * 4 + 3] = __float2half_rn(v.w);
    }
    __syncthreads();
#pragma unroll
    for (int k = 0; k < 4; ++k) {
        int lin = u + k * 256;
        int p = lin >> 4, tq = lin & 15;
        uint32_t w0 = (uint32_t)__half_as_ushort(st[(tq * 4 + 0) * 68 + p])
                    | ((uint32_t)__half_as_ushort(st[(tq * 4 + 1) * 68 + p]) << 16);
        uint32_t w1 = (uint32_t)__half_as_ushort(st[(tq * 4 + 2) * 68 + p])
                    | ((uint32_t)__half_as_ushort(st[(tq * 4 + 3) * 68 + p]) << 16);
        *(uint2*)(g_Xt + ((size_t)(bh * 64 + p)) * 1024 + t0 + tq * 4) = make_uint2(w0, w1);
    }
}

// ---------------------------------------------------------------------------
// Main kernel: block = (r2, bh), 128 rows, 16 warps (8 row-groups x 2 j-halves).
// fp16 single-pass both stages. cp.async 4-deep pipeline, prefetch distance 2,
// one __syncthreads per col-tile.
// ---------------------------------------------------------------------------
__global__ void __launch_bounds__(THREADS, 1)
ssd_mma_kernel(const float* __restrict__ Lm, const float* __restrict__ msfp,
               float* __restrict__ Yg)
{
    extern __shared__ char smb[];
    float* ecolb = (float*)(smb + O_ECOL);
    const uint32_t sb = smem_u32(smb);

    const int r2 = 7 - (int)blockIdx.x;
    const int bh = blockIdx.y;
    const int b = bh >> 5, h = bh & 31;
    const int tid = threadIdx.x;
    const int w = tid >> 5, lane = tid & 31;
    const int wr = w & 7;
    const int joff = (w >> 3) * 32;
    const float msf = *msfp;
    const float* acs = g_Acs + (size_t)bh * T_DIM;
    const int ncols = 2 * r2 + 2;
    const int row0 = r2 * 128;

    // ---- load C tile (fp16, preconverted) ----
    {
        const __half* csrc = g_Ch + ((size_t)bh * T_DIM + row0) * N_DIM;
#pragma unroll
        for (int u = 0; u < 4; ++u) {
            int idx = tid + u * THREADS;
            int row = idx >> 4, ch = idx & 15;
            *(uint4*)(smb + O_C + row * PCH + ch * 16) =
                *(const uint4*)(csrc + (size_t)row * N_DIM + ch * 8);
        }
    }

    auto issueTile = [&](int c) {
        int buf = c & 3;
        uint32_t bdst = sb + O_B + buf * 17408;
        const __half* bsrc = g_Bh + ((size_t)bh * T_DIM + c * 64) * N_DIM;
#pragma unroll
        for (int u = 0; u < 2; ++u) {
            int idx = tid + u * THREADS;
            int row = idx >> 4, ch = idx & 15;
            CP_ASYNC16(bdst + row * PCH + ch * 16, bsrc + (size_t)row * N_DIM + ch * 8);
        }
        uint32_t xdst = sb + O_X + buf * 9216;
        const __half* xsrc = g_Xt + (size_t)bh * 64 * T_DIM + c * 64;
        {
            int p = tid >> 3, ch = tid & 7;
            CP_ASYNC16(xdst + p * PXH + ch * 16, xsrc + (size_t)p * T_DIM + ch * 8);
        }
    };

    // lane geometry
    const int g = lane >> 3;
    const int lrow = (g & 1) * 8 + (lane & 7);
    const int lcolB = (g >> 1) * 16;
    const uint32_t aC = sb + O_C + (wr * 16 + lrow) * PCH + lcolB;

    const int ig0 = row0 + wr * 16 + (lane >> 2);
    const int ig1 = ig0 + 8;
    const float av0 = acs[ig0], av1 = acs[ig1];
    const int jmaxRow = row0 + wr * 16 + 15;
    const float* lr0 = Lm + ((size_t)bh * T_DIM + ig0) * T_DIM;
    const float* lr1 = lr0 + 8 * T_DIM;

    float yacc[8][4];
#pragma unroll
    for (int i = 0; i < 8; i++)
#pragma unroll
        for (int e = 0; e < 4; e++) yacc[i][e] = 0.f;

    // ---- prologue: prefetch tiles 0 and 1 (ncols >= 2 always) ----
    issueTile(0); CP_COMMIT();
    issueTile(1); CP_COMMIT();
    if (tid < 64) {
        ecolb[tid]      = __expf(acs[0]  - acs[tid]);
        ecolb[64 + tid] = __expf(acs[64] - acs[64 + tid]);
    }

    for (int c = 0; c < ncols; ++c) {
        if (c + 2 < ncols) {
            issueTile(c + 2);
            if (tid < 64) {
                int j0 = (c + 2) * 64;
                ecolb[((c + 2) & 3) * 64 + tid] = __expf(__ldg(acs + j0) - __ldg(acs + j0 + tid));
            }
        }
        CP_COMMIT();
        CP_WAIT2();
        __syncthreads();

        if (c * 64 <= jmaxRow) {
            // ---- Lm prefetch ----
            float2 L0[4], L1[4];
            const float* l0p = lr0 + c * 64 + joff;
            const float* l1p = lr1 + c * 64 + joff;
#pragma unroll
            for (int nf = 0; nf < 4; ++nf) {
                int jl = 8 * nf + (lane & 3) * 2;
                L0[nf] = __ldcs((const float2*)(l0p + jl));
                L1[nf] = __ldcs((const float2*)(l1p + jl));
            }
            const float aj0 = __ldg(acs + c * 64);

            // ---- Stage 1: S(16x32) = C·B^T ----
            float sacc[4][4];
#pragma unroll
            for (int i = 0; i < 4; i++)
#pragma unroll
                for (int e = 0; e < 4; e++) sacc[i][e] = 0.f;

            const uint32_t bBase = sb + O_B + (c & 3) * 17408 + (joff + lrow) * PCH + lcolB;
#pragma unroll
            for (int ks = 0; ks < 8; ++ks) {
                uint32_t a0, a1, a2, a3;
                ldsm4(a0, a1, a2, a3, aC + ks * 32);
#pragma unroll
                for (int nf2 = 0; nf2 < 2; ++nf2) {
                    uint32_t b0, b1, b2, b3;
                    ldsm4(b0, b1, b2, b3, bBase + nf2 * (16 * PCH) + ks * 32);
                    mma16816(sacc[2 * nf2],     a0, a1, a2, a3, b0, b2);
                    mma16816(sacc[2 * nf2 + 1], a0, a1, a2, a3, b1, b3);
                }
            }

            // ---- Epilogue: mask + round Ms to fp16 A-frags ----
            const float erow0 = __expf(av0 - aj0);
            const float erow1 = __expf(av1 - aj0);
            const float* ecol = ecolb + (c & 3) * 64;
            uint32_t mhi[8];
#pragma unroll
            for (int nf = 0; nf < 4; ++nf) {
                int jl = joff + 8 * nf + (lane & 3) * 2;
                int jgv = c * 64 + jl;
                float2 ec = *(const float2*)(ecol + jl);
                float f00 = (jgv     <= ig0) ? fmaf(msf, L0[nf].x, erow0 * ec.x) : 0.f;
                float f01 = (jgv + 1 <= ig0) ? fmaf(msf, L0[nf].y, erow0 * ec.y) : 0.f;
                float f10 = (jgv     <= ig1) ? fmaf(msf, L1[nf].x, erow1 * ec.x) : 0.f;
                float f11 = (jgv + 1 <= ig1) ? fmaf(msf, L1[nf].y, erow1 * ec.y) : 0.f;
                int ks = nf >> 1, part = nf & 1;
                int i0 = ks * 4 + part * 2;
                mhi[i0]     = pack_h2(sacc[nf][0] * f00, sacc[nf][1] * f01);
                mhi[i0 + 1] = pack_h2(sacc[nf][2] * f10, sacc[nf][3] * f11);
            }

            // ---- Stage 2: Y += Ms·X ----
            const uint32_t xBase = sb + O_X + (c & 3) * 9216 + lrow * PXH + joff * 2 + lcolB;
#pragma unroll
            for (int ks = 0; ks < 2; ++ks) {
#pragma unroll
                for (int pf2 = 0; pf2 < 4; ++pf2) {
                    uint32_t b0, b1, b2, b3;
                    ldsm4(b0, b1, b2, b3, xBase + pf2 * (16 * PXH) + ks * 32);
                    mma16816(yacc[2 * pf2],     mhi[4 * ks], mhi[4 * ks + 1], mhi[4 * ks + 2], mhi[4 * ks + 3], b0, b2);
                    mma16816(yacc[2 * pf2 + 1], mhi[4 * ks], mhi[4 * ks + 1], mhi[4 * ks + 2], mhi[4 * ks + 3], b1, b3);
                }
            }
        }
    }

    // ---- reduce warp pairs (w, w+8) and write Y ----
    __syncthreads();
    float* stag = (float*)(smb + O_B);
    if (w >= 8) {
        float* d = stag + ((w - 8) * 32 + lane) * 32;
#pragma unroll
        for (int i = 0; i < 8; ++i)
#pragma unroll
            for (int e = 0; e < 4; ++e) d[i * 4 + e] = yacc[i][e];
    }
    __syncthreads();
    if (w < 8) {
        const float* s = stag + (w * 32 + lane) * 32;
        float* yr0 = Yg + ((size_t)((b * T_DIM + ig0) * H_DIM) + h) * P_DIM;
        float* yr1 = Yg + ((size_t)((b * T_DIM + ig1) * H_DIM) + h) * P_DIM;
#pragma unroll
        for (int pf = 0; pf < 8; ++pf) {
            int p0 = 8 * pf + (lane & 3) * 2;
            *(float2*)(yr0 + p0) = make_float2(yacc[pf][0] + s[pf * 4 + 0], yacc[pf][1] + s[pf * 4 + 1]);
            *(float2*)(yr1 + p0) = make_float2(yacc[pf][2] + s[pf * 4 + 2], yacc[pf][3] + s[pf * 4 + 3]);
        }
    }
}

// ---------------------------------------------------------------------------
// final_state partials + reduce (fp32, unchanged)
// ---------------------------------------------------------------------------
#define PC 132
#define PX 68
__global__ void __launch_bounds__(256) state_kernel(
    const float* __restrict__ xg, const float* __restrict__ Bg)
{
    int split = blockIdx.x;
    int bh    = blockIdx.y;
    int b = bh >> 5, h = bh & 31;
    const float* acs = g_Acs + (size_t)bh * T_DIM;
    float atot = acs[T_DIM - 1];

    __shared__ float sx[32 * PX];
    __shared__ float sb[32 * PC];
    __shared__ float sd[32];

    int tid = threadIdx.x;
    int i2 = tid >> 4, j2 = tid & 15;
    float acc[4][8];
#pragma unroll
    for (int a = 0; a < 4; a++)
#pragma unroll
        for (int c2 = 0; c2 < 8; c2++) acc[a][c2] = 0.f;

    const int tspan = T_DIM / NSPLIT;
    const int t0base = split * tspan;
    for (int t0 = t0base; t0 < t0base + tspan; t0 += 32) {
        __syncthreads();
        for (int idx = tid; idx < 32 * 16; idx += 256) {
            int row = idx >> 4, q = idx & 15;
            *(float4*)(sx + row * PX + q * 4) =
                *(const float4*)(xg + ((size_t)((b * T_DIM + t0 + row) * H_DIM) + h) * P_DIM + q * 4);
        }
        for (int idx = tid; idx < 32 * 32; idx += 256) {
            int row = idx >> 5, q = idx & 31;
            *(float4*)(sb + row * PC + q * 4) =
                *(const float4*)(Bg + ((size_t)((b * T_DIM + t0 + row) * H_DIM) + h) * N_DIM + q * 4);
        }
        if (tid < 32) sd[tid] = __expf(atot - acs[t0 + tid]);
        __syncthreads();

        for (int tt = 0; tt < 32; ++tt) {
            float d = sd[tt];
            float a0[4], b0[8];
#pragma unroll
            for (int di = 0; di < 4; di++) a0[di] = sx[tt * PX + i2 + 16 * di] * d;
#pragma unroll
            for (int dj = 0; dj < 8; dj++) b0[dj] = sb[tt * PC + j2 + 16 * dj];
#pragma unroll
            for (int di = 0; di < 4; di++)
#pragma unroll
                for (int dj = 0; dj < 8; dj++)
                    acc[di][dj] += a0[di] * b0[dj];
        }
    }

    float* outp = g_part + ((size_t)split * BH + bh) * (P_DIM * N_DIM);
#pragma unroll
    for (int di = 0; di < 4; di++)
#pragma unroll
        for (int dj = 0; dj < 8; dj++)
            outp[(i2 + 16 * di) * N_DIM + (j2 + 16 * dj)] = acc[di][dj];
}

__global__ void reduce_kernel(float* __restrict__ out) {
    int idx = blockIdx.x * 256 + threadIdx.x;
    if (idx < FS_SIZE) {
        float s = 0.f;
#pragma unroll
        for (int sp = 0; sp < NSPLIT; ++sp)
            s += g_part[(size_t)sp * FS_SIZE + idx];
        out[Y_SIZE + idx] = s;
    }
}

// ---------------------------------------------------------------------------
extern "C" void kernel_launch(void* const* d_in, const int* in_sizes, int n_in,
                              void* d_out, int out_size) {
    const float* xg  = (const float*)d_in[0];
    const float* Ag  = (const float*)d_in[1];
    const float* Bg  = (const float*)d_in[2];
    const float* Cg  = (const float*)d_in[3];
    const float* Lm  = (const float*)d_in[4];
    const float* msf = (const float*)d_in[5];
    float* out = (float*)d_out;

    acs_kernel<<<BH, 1024>>>(Ag);
    conv_bc_kernel<<<dim3(8192, 2), 256>>>(Bg, Cg);
    conv_x_kernel<<<dim3(16, BH), 256>>>(xg);

    cudaFuncSetAttribute(ssd_mma_kernel,
                         cudaFuncAttributeMaxDynamicSharedMemorySize, SMEM_BYTES);
    ssd_mma_kernel<<<dim3(8, BH), THREADS, SMEM_BYTES>>>(Lm, msf, out);

    state_kernel<<<dim3(NSPLIT, BH), 256>>>(xg, Bg);
    reduce_kernel<<<(FS_SIZE + 255) / 256, 256>>>(out);
}

// round 10
// speedup vs baseline: 1.5957x; 1.5957x over previous
#include <cuda_runtime.h>
#include <cuda_fp16.h>
#include <cstdint>

// Problem constants
#define B_DIM 2
#define T_DIM 1024
#define H_DIM 32
#define P_DIM 64
#define N_DIM 128
#define BH (B_DIM * H_DIM)
#define Y_SIZE (B_DIM * T_DIM * H_DIM * P_DIM)
#define FS_SIZE (BH * P_DIM * N_DIM)
#define NSPLIT 8

__device__ float g_Acs[BH * T_DIM];
__device__ float g_part[NSPLIT * FS_SIZE];
__device__ __align__(16) __half g_Bh[BH * T_DIM * N_DIM];   // [bh][t][n] 16MB
__device__ __align__(16) __half g_Xt[BH * P_DIM * T_DIM];   // [bh][p][t]  8MB

// ---------------- helpers ----------------
__device__ __forceinline__ uint32_t smem_u32(const void* p) {
    uint32_t a;
    asm("{ .reg .u64 t; cvta.to.shared.u64 t, %1; cvt.u32.u64 %0, t; }" : "=r"(a) : "l"(p));
    return a;
}
__device__ __forceinline__ void ldsm4(uint32_t& r0, uint32_t& r1, uint32_t& r2, uint32_t& r3, uint32_t addr) {
    asm volatile("ldmatrix.sync.aligned.m8n8.x4.shared.b16 {%0,%1,%2,%3}, [%4];"
                 : "=r"(r0), "=r"(r1), "=r"(r2), "=r"(r3) : "r"(addr));
}
__device__ __forceinline__ void mma16816(float* d, uint32_t a0, uint32_t a1, uint32_t a2, uint32_t a3,
                                         uint32_t b0, uint32_t b1) {
    asm volatile("mma.sync.aligned.m16n8k16.row.col.f32.f16.f16.f32 "
                 "{%0,%1,%2,%3}, {%4,%5,%6,%7}, {%8,%9}, {%0,%1,%2,%3};"
                 : "+f"(d[0]), "+f"(d[1]), "+f"(d[2]), "+f"(d[3])
                 : "r"(a0), "r"(a1), "r"(a2), "r"(a3), "r"(b0), "r"(b1));
}
__device__ __forceinline__ uint32_t pack_h2(float x, float y) {
    uint32_t r;
    asm("cvt.rn.f16x2.f32 %0, %1, %2;" : "=r"(r) : "f"(y), "f"(x));
    return r;
}
#define CP_ASYNC16(dst, src) \
    asm volatile("cp.async.cg.shared.global [%0], [%1], 16;" :: "r"(dst), "l"(src))
#define CP_COMMIT()  asm volatile("cp.async.commit_group;" ::: "memory")
#define CP_WAIT0()   asm volatile("cp.async.wait_group 0;" ::: "memory")

// SMEM layout
#define PCH 272
#define PXH 144
#define O_ECOL 0                          // 2 x 64 floats
#define O_C    1024                       // 128*PCH = 34816
#define O_B    (O_C + 128 * PCH)          // 35840 ; 2 bufs x 17408
#define O_X    (O_B + 2 * 17408)          // 70656 ; 2 bufs x 9216
#define SMEM_BYTES (O_X + 2 * 9216)       // 89088

#define THREADS 256

// ---------------------------------------------------------------------------
__global__ void __launch_bounds__(1024) acs_kernel(const float* __restrict__ A) {
    int bh = blockIdx.x;
    int b = bh >> 5, h = bh & 31;
    __shared__ float buf[2][T_DIM];
    int t = threadIdx.x;
    buf[0][t] = A[(size_t)(b * T_DIM + t) * H_DIM + h];
    __syncthreads();
    int src = 0;
    for (int off = 1; off < T_DIM; off <<= 1) {
        float v = buf[src][t];
        if (t >= off) v += buf[src][t - off];
        buf[src ^ 1][t] = v;
        src ^= 1;
        __syncthreads();
    }
    g_Acs[bh * T_DIM + t] = buf[src][t];
}

// ---------------------------------------------------------------------------
// Preconvert + transpose X: [b,t,h,p] fp32 -> [bh][p][t] fp16
// ---------------------------------------------------------------------------
__global__ void __launch_bounds__(256) conv_x_kernel(const float* __restrict__ xg) {
    int tb = blockIdx.x;
    int bh = blockIdx.y;
    int b = bh >> 5, h = bh & 31;
    __shared__ __half st[64 * 68];
    int u = threadIdx.x;
    int t0 = tb * 64;
#pragma unroll
    for (int k = 0; k < 4; ++k) {
        int lin = u + k * 256;
        int i = lin >> 4, fq = lin & 15;
        float4 v = *(const float4*)(xg + ((size_t)((b * 1024 + t0 + i) * 32 + h)) * 64 + fq * 4);
        st[i * 68 + fq * 4 + 0] = __float2half_rn(v.x);
        st[i * 68 + fq * 4 + 1] = __float2half_rn(v.y);
        st[i * 68 + fq * 4 + 2] = __float2half_rn(v.z);
        st[i * 68 + fq * 4 + 3] = __float2half_rn(v.w);
    }
    __syncthreads();
#pragma unroll
    for (int k = 0; k < 4; ++k) {
        int lin = u + k * 256;
        int p = lin >> 4, tq = lin & 15;
        uint32_t w0 = (uint32_t)__half_as_ushort(st[(tq * 4 + 0) * 68 + p])
                    | ((uint32_t)__half_as_ushort(st[(tq * 4 + 1) * 68 + p]) << 16);
        uint32_t w1 = (uint32_t)__half_as_ushort(st[(tq * 4 + 2) * 68 + p])
                    | ((uint32_t)__half_as_ushort(st[(tq * 4 + 3) * 68 + p]) << 16);
        *(uint2*)(g_Xt + ((size_t)(bh * 64 + p)) * 1024 + t0 + tq * 4) = make_uint2(w0, w1);
    }
}

// ---------------------------------------------------------------------------
// state_kernel: final_state partials; ALSO emits fp16 g_Bh (it reads B anyway).
// ---------------------------------------------------------------------------
#define PC 132
#define PX 68
__global__ void __launch_bounds__(256) state_kernel(
    const float* __restrict__ xg, const float* __restrict__ Bg)
{
    int split = blockIdx.x;
    int bh    = blockIdx.y;
    int b = bh >> 5, h = bh & 31;
    const float* acs = g_Acs + (size_t)bh * T_DIM;
    float atot = acs[T_DIM - 1];

    __shared__ float sx[32 * PX];
    __shared__ float sb[32 * PC];
    __shared__ float sd[32];

    int tid = threadIdx.x;
    int i2 = tid >> 4, j2 = tid & 15;
    float acc[4][8];
#pragma unroll
    for (int a = 0; a < 4; a++)
#pragma unroll
        for (int c2 = 0; c2 < 8; c2++) acc[a][c2] = 0.f;

    const int tspan = T_DIM / NSPLIT;
    const int t0base = split * tspan;
    for (int t0 = t0base; t0 < t0base + tspan; t0 += 32) {
        __syncthreads();
        for (int idx = tid; idx < 32 * 16; idx += 256) {
            int row = idx >> 4, q = idx & 15;
            *(float4*)(sx + row * PX + q * 4) =
                *(const float4*)(xg + ((size_t)((b * T_DIM + t0 + row) * H_DIM) + h) * P_DIM + q * 4);
        }
        for (int idx = tid; idx < 32 * 32; idx += 256) {
            int row = idx >> 5, q = idx & 31;
            float4 v = *(const float4*)(Bg + ((size_t)((b * T_DIM + t0 + row) * H_DIM) + h) * N_DIM + q * 4);
            *(float4*)(sb + row * PC + q * 4) = v;
            // fp16 emission for the main kernel
            *(uint2*)(g_Bh + ((size_t)(bh * T_DIM + t0 + row)) * N_DIM + q * 4) =
                make_uint2(pack_h2(v.x, v.y), pack_h2(v.z, v.w));
        }
        if (tid < 32) sd[tid] = __expf(atot - acs[t0 + tid]);
        __syncthreads();

        for (int tt = 0; tt < 32; ++tt) {
            float d = sd[tt];
            float a0[4], b0[8];
#pragma unroll
            for (int di = 0; di < 4; di++) a0[di] = sx[tt * PX + i2 + 16 * di] * d;
#pragma unroll
            for (int dj = 0; dj < 8; dj++) b0[dj] = sb[tt * PC + j2 + 16 * dj];
#pragma unroll
            for (int di = 0; di < 4; di++)
#pragma unroll
                for (int dj = 0; dj < 8; dj++)
                    acc[di][dj] += a0[di] * b0[dj];
        }
    }

    float* outp = g_part + ((size_t)split * BH + bh) * (P_DIM * N_DIM);
#pragma unroll
    for (int di = 0; di < 4; di++)
#pragma unroll
        for (int dj = 0; dj < 8; dj++)
            outp[(i2 + 16 * di) * N_DIM + (j2 + 16 * dj)] = acc[di][dj];
}

// ---------------------------------------------------------------------------
// Main kernel: block = (r2, bh), 128 rows, 8 warps, warp = 16 rows x 64 j.
// 2 CTAs/SM. fp16 single-pass both stages. 2-deep cp.async, 1 sync/iter.
// ---------------------------------------------------------------------------
__global__ void __launch_bounds__(THREADS, 2)
ssd_mma_kernel(const float* __restrict__ Cg, const float* __restrict__ Lm,
               const float* __restrict__ msfp, float* __restrict__ Yg)
{
    extern __shared__ char smb[];
    float* ecolb = (float*)(smb + O_ECOL);
    const uint32_t sb = smem_u32(smb);

    const int r2 = 7 - (int)blockIdx.x;
    const int bh = blockIdx.y;
    const int b = bh >> 5, h = bh & 31;
    const int tid = threadIdx.x;
    const int w = tid >> 5, lane = tid & 31;
    const float msf = *msfp;
    const float* acs = g_Acs + (size_t)bh * T_DIM;
    const int ncols = 2 * r2 + 2;
    const int row0 = r2 * 128;

    // ---- load + round C (128 x 128 fp32 -> fp16) ----
#pragma unroll 4
    for (int u = 0; u < 16; ++u) {
        int idx = tid + u * THREADS;
        int row = idx >> 5, q = idx & 31;
        float4 v = *(const float4*)(Cg + ((size_t)((b * T_DIM + row0 + row) * H_DIM) + h) * N_DIM + q * 4);
        *(uint2*)(smb + O_C + row * PCH + q * 8) = make_uint2(pack_h2(v.x, v.y), pack_h2(v.z, v.w));
    }

    auto issueTile = [&](int c) {
        int buf = c & 1;
        uint32_t bdst = sb + O_B + buf * 17408;
        const __half* bsrc = g_Bh + ((size_t)bh * T_DIM + c * 64) * N_DIM;
#pragma unroll
        for (int u = 0; u < 4; ++u) {
            int idx = tid + u * THREADS;
            int row = idx >> 4, ch = idx & 15;
            CP_ASYNC16(bdst + row * PCH + ch * 16, bsrc + (size_t)row * N_DIM + ch * 8);
        }
        uint32_t xdst = sb + O_X + buf * 9216;
        const __half* xsrc = g_Xt + (size_t)bh * 64 * T_DIM + c * 64;
#pragma unroll
        for (int u = 0; u < 2; ++u) {
            int idx = tid + u * THREADS;
            int p = idx >> 3, ch = idx & 7;
            CP_ASYNC16(xdst + p * PXH + ch * 16, xsrc + (size_t)p * T_DIM + ch * 8);
        }
    };

    // lane geometry
    const int g = lane >> 3;
    const int lrow = (g & 1) * 8 + (lane & 7);
    const int lcolB = (g >> 1) * 16;
    const uint32_t aC = sb + O_C + (w * 16 + lrow) * PCH + lcolB;

    const int ig0 = row0 + w * 16 + (lane >> 2);
    const int ig1 = ig0 + 8;
    const float av0 = acs[ig0], av1 = acs[ig1];
    const int jmaxRow = row0 + w * 16 + 15;
    const float* lr0 = Lm + ((size_t)bh * T_DIM + ig0) * T_DIM;
    const float* lr1 = lr0 + 8 * T_DIM;

    float yacc[8][4];
#pragma unroll
    for (int i = 0; i < 8; i++)
#pragma unroll
        for (int e = 0; e < 4; e++) yacc[i][e] = 0.f;

    // ---- prologue: prefetch tile 0 + ecol[0] ----
    issueTile(0); CP_COMMIT();
    if (tid < 64) ecolb[tid] = __expf(acs[0] - acs[tid]);

    for (int c = 0; c < ncols; ++c) {
        CP_WAIT0();          // tile c resident
        __syncthreads();     // + everyone done with buffer c-1, ecol[c] visible
        if (c + 1 < ncols) {
            issueTile(c + 1); CP_COMMIT();   // fills buffer (c+1)&1, overlaps compute
            if (tid < 64) {
                int j0 = (c + 1) * 64;
                ecolb[((c + 1) & 1) * 64 + tid] = __expf(__ldg(acs + j0) - __ldg(acs + j0 + tid));
            }
        }

        if (c * 64 <= jmaxRow) {
            const float aj0 = __ldg(acs + c * 64);
            // ---- Lm prefetch, first half ----
            float2 L0[8], L1[8];
            const float* l0p = lr0 + c * 64;
            const float* l1p = lr1 + c * 64;
#pragma unroll
            for (int nf = 0; nf < 4; ++nf) {
                int jl = 8 * nf + (lane & 3) * 2;
                L0[nf] = __ldcs((const float2*)(l0p + jl));
                L1[nf] = __ldcs((const float2*)(l1p + jl));
            }

            // ---- Stage 1: S(16x64) = C·B^T ----
            float sacc[8][4];
#pragma unroll
            for (int i = 0; i < 8; i++)
#pragma unroll
                for (int e = 0; e < 4; e++) sacc[i][e] = 0.f;

            const uint32_t bBase = sb + O_B + (c & 1) * 17408 + lrow * PCH + lcolB;
#pragma unroll
            for (int ks = 0; ks < 8; ++ks) {
                uint32_t a0, a1, a2, a3;
                ldsm4(a0, a1, a2, a3, aC + ks * 32);
#pragma unroll
                for (int nf2 = 0; nf2 < 4; ++nf2) {
                    uint32_t b0, b1, b2, b3;
                    ldsm4(b0, b1, b2, b3, bBase + nf2 * (16 * PCH) + ks * 32);
                    mma16816(sacc[2 * nf2],     a0, a1, a2, a3, b0, b2);
                    mma16816(sacc[2 * nf2 + 1], a0, a1, a2, a3, b1, b3);
                }
            }

            // ---- Lm prefetch, second half ----
#pragma unroll
            for (int nf = 4; nf < 8; ++nf) {
                int jl = 8 * nf + (lane & 3) * 2;
                L0[nf] = __ldcs((const float2*)(l0p + jl));
                L1[nf] = __ldcs((const float2*)(l1p + jl));
            }

            // ---- Epilogue: mask + round Ms to fp16 A-frags ----
            const float erow0 = __expf(av0 - aj0);
            const float erow1 = __expf(av1 - aj0);
            const float* ecol = ecolb + (c & 1) * 64;
            uint32_t mhi[16];
#pragma unroll
            for (int nf = 0; nf < 8; ++nf) {
                int jl = 8 * nf + (lane & 3) * 2;
                int jgv = c * 64 + jl;
                float2 ec = *(const float2*)(ecol + jl);
                float f00 = (jgv     <= ig0) ? fmaf(msf, L0[nf].x, erow0 * ec.x) : 0.f;
                float f01 = (jgv + 1 <= ig0) ? fmaf(msf, L0[nf].y, erow0 * ec.y) : 0.f;
                float f10 = (jgv     <= ig1) ? fmaf(msf, L1[nf].x, erow1 * ec.x) : 0.f;
                float f11 = (jgv + 1 <= ig1) ? fmaf(msf, L1[nf].y, erow1 * ec.y) : 0.f;
                int ks = nf >> 1, part = nf & 1;
                int i0 = ks * 4 + part * 2;
                mhi[i0]     = pack_h2(sacc[nf][0] * f00, sacc[nf][1] * f01);
                mhi[i0 + 1] = pack_h2(sacc[nf][2] * f10, sacc[nf][3] * f11);
            }

            // ---- Stage 2: Y += Ms·X (K=64) ----
            const uint32_t xBase = sb + O_X + (c & 1) * 9216 + lrow * PXH + lcolB;
#pragma unroll
            for (int ks = 0; ks < 4; ++ks) {
#pragma unroll
                for (int pf2 = 0; pf2 < 4; ++pf2) {
                    uint32_t b0, b1, b2, b3;
                    ldsm4(b0, b1, b2, b3, xBase + pf2 * (16 * PXH) + ks * 32);
                    mma16816(yacc[2 * pf2],     mhi[4 * ks], mhi[4 * ks + 1], mhi[4 * ks + 2], mhi[4 * ks + 3], b0, b2);
                    mma16816(yacc[2 * pf2 + 1], mhi[4 * ks], mhi[4 * ks + 1], mhi[4 * ks + 2], mhi[4 * ks + 3], b1, b3);
                }
            }
        }
    }

    // ---- write Y (each warp owns its 16 rows fully) ----
    float* yr0 = Yg + ((size_t)((b * T_DIM + ig0) * H_DIM) + h) * P_DIM;
    float* yr1 = Yg + ((size_t)((b * T_DIM + ig1) * H_DIM) + h) * P_DIM;
#pragma unroll
    for (int pf = 0; pf < 8; ++pf) {
        int p0 = 8 * pf + (lane & 3) * 2;
        *(float2*)(yr0 + p0) = make_float2(yacc[pf][0], yacc[pf][1]);
        *(float2*)(yr1 + p0) = make_float2(yacc[pf][2], yacc[pf][3]);
    }
}

__global__ void reduce_kernel(float* __restrict__ out) {
    int idx = blockIdx.x * 256 + threadIdx.x;
    if (idx < FS_SIZE) {
        float s = 0.f;
#pragma unroll
        for (int sp = 0; sp < NSPLIT; ++sp)
            s += g_part[(size_t)sp * FS_SIZE + idx];
        out[Y_SIZE + idx] = s;
    }
}

// ---------------------------------------------------------------------------
extern "C" void kernel_launch(void* const* d_in, const int* in_sizes, int n_in,
                              void* d_out, int out_size) {
    const float* xg  = (const float*)d_in[0];
    const float* Ag  = (const float*)d_in[1];
    const float* Bg  = (const float*)d_in[2];
    const float* Cg  = (const float*)d_in[3];
    const float* Lm  = (const float*)d_in[4];
    const float* msf = (const float*)d_in[5];
    float* out = (float*)d_out;

    acs_kernel<<<BH, 1024>>>(Ag);
    state_kernel<<<dim3(NSPLIT, BH), 256>>>(xg, Bg);   // also emits g_Bh
    conv_x_kernel<<<dim3(16, BH), 256>>>(xg);          // emits g_Xt

    cudaFuncSetAttribute(ssd_mma_kernel,
                         cudaFuncAttributeMaxDynamicSharedMemorySize, SMEM_BYTES);
    ssd_mma_kernel<<<dim3(8, BH), THREADS, SMEM_BYTES>>>(Cg, Lm, msf, out);

    reduce_kernel<<<(FS_SIZE + 255) / 256, 256>>>(out);
}

// round 11
// speedup vs baseline: 1.9421x; 1.2170x over previous
#include <cuda_runtime.h>
#include <cuda_fp16.h>
#include <cstdint>

// Problem constants
#define B_DIM 2
#define T_DIM 1024
#define H_DIM 32
#define P_DIM 64
#define N_DIM 128
#define BH (B_DIM * H_DIM)
#define Y_SIZE (B_DIM * T_DIM * H_DIM * P_DIM)
#define FS_SIZE (BH * P_DIM * N_DIM)

__device__ float g_Acs[BH * T_DIM];
__device__ __align__(16) __half g_Bh[BH * T_DIM * N_DIM];   // [bh][t][n] 16MB
__device__ __align__(16) __half g_Xt[BH * P_DIM * T_DIM];   // [bh][p][t]  8MB
__device__ __align__(16) __half g_Xd[BH * P_DIM * T_DIM];   // [bh][p][t] decay-scaled, 8MB

// ---------------- helpers ----------------
__device__ __forceinline__ uint32_t smem_u32(const void* p) {
    uint32_t a;
    asm("{ .reg .u64 t; cvta.to.shared.u64 t, %1; cvt.u32.u64 %0, t; }" : "=r"(a) : "l"(p));
    return a;
}
__device__ __forceinline__ void ldsm4(uint32_t& r0, uint32_t& r1, uint32_t& r2, uint32_t& r3, uint32_t addr) {
    asm volatile("ldmatrix.sync.aligned.m8n8.x4.shared.b16 {%0,%1,%2,%3}, [%4];"
                 : "=r"(r0), "=r"(r1), "=r"(r2), "=r"(r3) : "r"(addr));
}
__device__ __forceinline__ void ldsm4t(uint32_t& r0, uint32_t& r1, uint32_t& r2, uint32_t& r3, uint32_t addr) {
    asm volatile("ldmatrix.sync.aligned.m8n8.x4.trans.shared.b16 {%0,%1,%2,%3}, [%4];"
                 : "=r"(r0), "=r"(r1), "=r"(r2), "=r"(r3) : "r"(addr));
}
__device__ __forceinline__ void mma16816(float* d, uint32_t a0, uint32_t a1, uint32_t a2, uint32_t a3,
                                         uint32_t b0, uint32_t b1) {
    asm volatile("mma.sync.aligned.m16n8k16.row.col.f32.f16.f16.f32 "
                 "{%0,%1,%2,%3}, {%4,%5,%6,%7}, {%8,%9}, {%0,%1,%2,%3};"
                 : "+f"(d[0]), "+f"(d[1]), "+f"(d[2]), "+f"(d[3])
                 : "r"(a0), "r"(a1), "r"(a2), "r"(a3), "r"(b0), "r"(b1));
}
__device__ __forceinline__ uint32_t pack_h2(float x, float y) {
    uint32_t r;
    asm("cvt.rn.f16x2.f32 %0, %1, %2;" : "=r"(r) : "f"(y), "f"(x));
    return r;
}
#define CP_ASYNC16(dst, src) \
    asm volatile("cp.async.cg.shared.global [%0], [%1], 16;" :: "r"(dst), "l"(src))
#define CP_COMMIT()  asm volatile("cp.async.commit_group;" ::: "memory")
#define CP_WAIT0()   asm volatile("cp.async.wait_group 0;" ::: "memory")

// SMEM layout (main kernel)
#define PCH 272
#define PXH 144
#define O_ECOL 0
#define O_C    1024
#define O_B    (O_C + 128 * PCH)          // 35840 ; 2 bufs x 17408
#define O_X    (O_B + 2 * 17408)          // 70656 ; 2 bufs x 9216
#define SMEM_BYTES (O_X + 2 * 9216)       // 89088

#define THREADS 256

// fs kernel smem
#define FS_OB 0                           // 2 bufs x 17408
#define FS_OX (2 * 17408)                 // 2 bufs x 9216
#define FS_SMEM (FS_OX + 2 * 9216)        // 53248

// ---------------------------------------------------------------------------
__global__ void __launch_bounds__(1024) acs_kernel(const float* __restrict__ A) {
    int bh = blockIdx.x;
    int b = bh >> 5, h = bh & 31;
    __shared__ float buf[2][T_DIM];
    int t = threadIdx.x;
    buf[0][t] = A[(size_t)(b * T_DIM + t) * H_DIM + h];
    __syncthreads();
    int src = 0;
    for (int off = 1; off < T_DIM; off <<= 1) {
        float v = buf[src][t];
        if (t >= off) v += buf[src][t - off];
        buf[src ^ 1][t] = v;
        src ^= 1;
        __syncthreads();
    }
    g_Acs[bh * T_DIM + t] = buf[src][t];
}

// ---------------------------------------------------------------------------
// conv_b: B [b,t,h,n] fp32 -> g_Bh [bh][t][n] fp16 (elementwise relayout)
// ---------------------------------------------------------------------------
__global__ void __launch_bounds__(256) conv_b_kernel(const float* __restrict__ Bg) {
    int lin = blockIdx.x * 256 + threadIdx.x;      // 2^21 threads
    int q = lin & 31;
    int h = (lin >> 5) & 31;
    int t = (lin >> 10) & 1023;
    int b = lin >> 20;
    float4 v = *(const float4*)(Bg + ((size_t)((b * 1024 + t) * 32 + h)) * 128 + q * 4);
    *(uint2*)(g_Bh + ((size_t)((b * 32 + h) * 1024 + t)) * 128 + q * 4) =
        make_uint2(pack_h2(v.x, v.y), pack_h2(v.z, v.w));
}

// ---------------------------------------------------------------------------
// conv_x: x [b,t,h,p] fp32 -> g_Xt [bh][p][t] fp16 AND g_Xd = fp16(d_t * x)
// ---------------------------------------------------------------------------
__global__ void __launch_bounds__(256) conv_x_kernel(const float* __restrict__ xg) {
    int tb = blockIdx.x;
    int bh = blockIdx.y;
    int b = bh >> 5, h = bh & 31;
    __shared__ float sxf[64 * 68];
    __shared__ float sd[64];
    int u = threadIdx.x;
    int t0 = tb * 64;
    const float* acs = g_Acs + (size_t)bh * T_DIM;
    if (u < 64) sd[u] = __expf(acs[T_DIM - 1] - acs[t0 + u]);
#pragma unroll
    for (int k = 0; k < 4; ++k) {
        int lin = u + k * 256;
        int i = lin >> 4, fq = lin & 15;
        float4 v = *(const float4*)(xg + ((size_t)((b * 1024 + t0 + i) * 32 + h)) * 64 + fq * 4);
        *(float4*)(sxf + i * 68 + fq * 4) = v;
    }
    __syncthreads();
#pragma unroll
    for (int k = 0; k < 4; ++k) {
        int lin = u + k * 256;
        int p = lin >> 4, tq = lin & 15;
        float v0 = sxf[(tq * 4 + 0) * 68 + p], v1 = sxf[(tq * 4 + 1) * 68 + p];
        float v2 = sxf[(tq * 4 + 2) * 68 + p], v3 = sxf[(tq * 4 + 3) * 68 + p];
        size_t o = ((size_t)(bh * 64 + p)) * 1024 + t0 + tq * 4;
        *(uint2*)(g_Xt + o) = make_uint2(pack_h2(v0, v1), pack_h2(v2, v3));
        float d0 = sd[tq * 4 + 0], d1 = sd[tq * 4 + 1], d2 = sd[tq * 4 + 2], d3 = sd[tq * 4 + 3];
        *(uint2*)(g_Xd + o) = make_uint2(pack_h2(v0 * d0, v1 * d1), pack_h2(v2 * d2, v3 * d3));
    }
}

// ---------------------------------------------------------------------------
// fs kernel: final_state[p,n] = sum_t Xd[p,t] * Bh[t,n]  (fp16 mma, K=1024)
// One CTA per bh, 8 warps, warp w owns n-block [16w, 16w+16).
// ---------------------------------------------------------------------------
__global__ void __launch_bounds__(256)
fs_kernel(float* __restrict__ out)
{
    extern __shared__ char smb[];
    const uint32_t sb = smem_u32(smb);
    const int bh = blockIdx.x;
    const int tid = threadIdx.x;
    const int w = tid >> 5, lane = tid & 31;
    const int nb = w * 16;
    const int g = lane >> 3;
    const int lrow = (g & 1) * 8 + (lane & 7);
    const int lcolB = (g >> 1) * 16;

    auto issueTile = [&](int c) {
        int buf = c & 1;
        uint32_t bdst = sb + FS_OB + buf * 17408;
        const __half* bsrc = g_Bh + ((size_t)bh * T_DIM + c * 64) * N_DIM;
#pragma unroll
        for (int u = 0; u < 4; ++u) {
            int idx = tid + u * 256;
            int row = idx >> 4, ch = idx & 15;
            CP_ASYNC16(bdst + row * PCH + ch * 16, bsrc + (size_t)row * N_DIM + ch * 8);
        }
        uint32_t xdst = sb + FS_OX + buf * 9216;
        const __half* xsrc = g_Xd + (size_t)bh * 64 * T_DIM + c * 64;
#pragma unroll
        for (int u = 0; u < 2; ++u) {
            int idx = tid + u * 256;
            int p = idx >> 3, ch = idx & 7;
            CP_ASYNC16(xdst + p * PXH + ch * 16, xsrc + (size_t)p * T_DIM + ch * 8);
        }
    };

    float facc[8][4];
#pragma unroll
    for (int i = 0; i < 8; i++)
#pragma unroll
        for (int e = 0; e < 4; e++) facc[i][e] = 0.f;

    issueTile(0); CP_COMMIT();
    for (int c = 0; c < 16; ++c) {
        CP_WAIT0();
        __syncthreads();
        if (c + 1 < 16) { issueTile(c + 1); CP_COMMIT(); }

        const uint32_t xBase = sb + FS_OX + (c & 1) * 9216;
        const uint32_t bBase = sb + FS_OB + (c & 1) * 17408;
#pragma unroll
        for (int ks = 0; ks < 4; ++ks) {
            // B fragments via trans ldsm: rows t, cols n -> lane gets (k pair, n)
            uint32_t r0, r1, r2, r3;
            ldsm4t(r0, r1, r2, r3,
                   bBase + (ks * 16 + (g & 1) * 8 + (lane & 7)) * PCH + nb * 2 + (g >> 1) * 16);
#pragma unroll
            for (int mt = 0; mt < 4; ++mt) {
                uint32_t a0, a1, a2, a3;
                ldsm4(a0, a1, a2, a3, xBase + (mt * 16 + lrow) * PXH + ks * 32 + lcolB);
                mma16816(facc[mt * 2 + 0], a0, a1, a2, a3, r0, r1);
                mma16816(facc[mt * 2 + 1], a0, a1, a2, a3, r2, r3);
            }
        }
        __syncthreads();
    }

    // write fs: out[Y_SIZE + (bh*64+p)*128 + n]
    float* fo = out + Y_SIZE + (size_t)bh * (P_DIM * N_DIM);
#pragma unroll
    for (int mt = 0; mt < 4; ++mt) {
        int p0 = mt * 16 + (lane >> 2);
#pragma unroll
        for (int nf = 0; nf < 2; ++nf) {
            int n0 = nb + nf * 8 + (lane & 3) * 2;
            *(float2*)(fo + (size_t)p0 * N_DIM + n0) =
                make_float2(facc[mt * 2 + nf][0], facc[mt * 2 + nf][1]);
            *(float2*)(fo + (size_t)(p0 + 8) * N_DIM + n0) =
                make_float2(facc[mt * 2 + nf][2], facc[mt * 2 + nf][3]);
        }
    }
}

// ---------------------------------------------------------------------------
// Main kernel: unchanged from R10 (98.7us). block = (r2, bh), 128 rows, 8 warps.
// ---------------------------------------------------------------------------
__global__ void __launch_bounds__(THREADS, 2)
ssd_mma_kernel(const float* __restrict__ Cg, const float* __restrict__ Lm,
               const float* __restrict__ msfp, float* __restrict__ Yg)
{
    extern __shared__ char smb[];
    float* ecolb = (float*)(smb + O_ECOL);
    const uint32_t sb = smem_u32(smb);

    const int r2 = 7 - (int)blockIdx.x;
    const int bh = blockIdx.y;
    const int b = bh >> 5, h = bh & 31;
    const int tid = threadIdx.x;
    const int w = tid >> 5, lane = tid & 31;
    const float msf = *msfp;
    const float* acs = g_Acs + (size_t)bh * T_DIM;
    const int ncols = 2 * r2 + 2;
    const int row0 = r2 * 128;

#pragma unroll 4
    for (int u = 0; u < 16; ++u) {
        int idx = tid + u * THREADS;
        int row = idx >> 5, q = idx & 31;
        float4 v = *(const float4*)(Cg + ((size_t)((b * T_DIM + row0 + row) * H_DIM) + h) * N_DIM + q * 4);
        *(uint2*)(smb + O_C + row * PCH + q * 8) = make_uint2(pack_h2(v.x, v.y), pack_h2(v.z, v.w));
    }

    auto issueTile = [&](int c) {
        int buf = c & 1;
        uint32_t bdst = sb + O_B + buf * 17408;
        const __half* bsrc = g_Bh + ((size_t)bh * T_DIM + c * 64) * N_DIM;
#pragma unroll
        for (int u = 0; u < 4; ++u) {
            int idx = tid + u * THREADS;
            int row = idx >> 4, ch = idx & 15;
            CP_ASYNC16(bdst + row * PCH + ch * 16, bsrc + (size_t)row * N_DIM + ch * 8);
        }
        uint32_t xdst = sb + O_X + buf * 9216;
        const __half* xsrc = g_Xt + (size_t)bh * 64 * T_DIM + c * 64;
#pragma unroll
        for (int u = 0; u < 2; ++u) {
            int idx = tid + u * THREADS;
            int p = idx >> 3, ch = idx & 7;
            CP_ASYNC16(xdst + p * PXH + ch * 16, xsrc + (size_t)p * T_DIM + ch * 8);
        }
    };

    const int g = lane >> 3;
    const int lrow = (g & 1) * 8 + (lane & 7);
    const int lcolB = (g >> 1) * 16;
    const uint32_t aC = sb + O_C + (w * 16 + lrow) * PCH + lcolB;

    const int ig0 = row0 + w * 16 + (lane >> 2);
    const int ig1 = ig0 + 8;
    const float av0 = acs[ig0], av1 = acs[ig1];
    const int jmaxRow = row0 + w * 16 + 15;
    const float* lr0 = Lm + ((size_t)bh * T_DIM + ig0) * T_DIM;
    const float* lr1 = lr0 + 8 * T_DIM;

    float yacc[8][4];
#pragma unroll
    for (int i = 0; i < 8; i++)
#pragma unroll
        for (int e = 0; e < 4; e++) yacc[i][e] = 0.f;

    issueTile(0); CP_COMMIT();
    if (tid < 64) ecolb[tid] = __expf(acs[0] - acs[tid]);

    for (int c = 0; c < ncols; ++c) {
        CP_WAIT0();
        __syncthreads();
        if (c + 1 < ncols) {
            issueTile(c + 1); CP_COMMIT();
            if (tid < 64) {
                int j0 = (c + 1) * 64;
                ecolb[((c + 1) & 1) * 64 + tid] = __expf(__ldg(acs + j0) - __ldg(acs + j0 + tid));
            }
        }

        if (c * 64 <= jmaxRow) {
            const float aj0 = __ldg(acs + c * 64);
            float2 L0[8], L1[8];
            const float* l0p = lr0 + c * 64;
            const float* l1p = lr1 + c * 64;
#pragma unroll
            for (int nf = 0; nf < 4; ++nf) {
                int jl = 8 * nf + (lane & 3) * 2;
                L0[nf] = __ldcs((const float2*)(l0p + jl));
                L1[nf] = __ldcs((const float2*)(l1p + jl));
            }

            float sacc[8][4];
#pragma unroll
            for (int i = 0; i < 8; i++)
#pragma unroll
                for (int e = 0; e < 4; e++) sacc[i][e] = 0.f;

            const uint32_t bBase = sb + O_B + (c & 1) * 17408 + lrow * PCH + lcolB;
#pragma unroll
            for (int ks = 0; ks < 8; ++ks) {
                uint32_t a0, a1, a2, a3;
                ldsm4(a0, a1, a2, a3, aC + ks * 32);
#pragma unroll
                for (int nf2 = 0; nf2 < 4; ++nf2) {
                    uint32_t b0, b1, b2, b3;
                    ldsm4(b0, b1, b2, b3, bBase + nf2 * (16 * PCH) + ks * 32);
                    mma16816(sacc[2 * nf2],     a0, a1, a2, a3, b0, b2);
                    mma16816(sacc[2 * nf2 + 1], a0, a1, a2, a3, b1, b3);
                }
            }

#pragma unroll
            for (int nf = 4; nf < 8; ++nf) {
                int jl = 8 * nf + (lane & 3) * 2;
                L0[nf] = __ldcs((const float2*)(l0p + jl));
                L1[nf] = __ldcs((const float2*)(l1p + jl));
            }

            const float erow0 = __expf(av0 - aj0);
            const float erow1 = __expf(av1 - aj0);
            const float* ecol = ecolb + (c & 1) * 64;
            uint32_t mhi[16];
#pragma unroll
            for (int nf = 0; nf < 8; ++nf) {
                int jl = 8 * nf + (lane & 3) * 2;
                int jgv = c * 64 + jl;
                float2 ec = *(const float2*)(ecol + jl);
                float f00 = (jgv     <= ig0) ? fmaf(msf, L0[nf].x, erow0 * ec.x) : 0.f;
                float f01 = (jgv + 1 <= ig0) ? fmaf(msf, L0[nf].y, erow0 * ec.y) : 0.f;
                float f10 = (jgv     <= ig1) ? fmaf(msf, L1[nf].x, erow1 * ec.x) : 0.f;
                float f11 = (jgv + 1 <= ig1) ? fmaf(msf, L1[nf].y, erow1 * ec.y) : 0.f;
                int ks = nf >> 1, part = nf & 1;
                int i0 = ks * 4 + part * 2;
                mhi[i0]     = pack_h2(sacc[nf][0] * f00, sacc[nf][1] * f01);
                mhi[i0 + 1] = pack_h2(sacc[nf][2] * f10, sacc[nf][3] * f11);
            }

            const uint32_t xBase = sb + O_X + (c & 1) * 9216 + lrow * PXH + lcolB;
#pragma unroll
            for (int ks = 0; ks < 4; ++ks) {
#pragma unroll
                for (int pf2 = 0; pf2 < 4; ++pf2) {
                    uint32_t b0, b1, b2, b3;
                    ldsm4(b0, b1, b2, b3, xBase + pf2 * (16 * PXH) + ks * 32);
                    mma16816(yacc[2 * pf2],     mhi[4 * ks], mhi[4 * ks + 1], mhi[4 * ks + 2], mhi[4 * ks + 3], b0, b2);
                    mma16816(yacc[2 * pf2 + 1], mhi[4 * ks], mhi[4 * ks + 1], mhi[4 * ks + 2], mhi[4 * ks + 3], b1, b3);
                }
            }
        }
    }

    float* yr0 = Yg + ((size_t)((b * T_DIM + ig0) * H_DIM) + h) * P_DIM;
    float* yr1 = Yg + ((size_t)((b * T_DIM + ig1) * H_DIM) + h) * P_DIM;
#pragma unroll
    for (int pf = 0; pf < 8; ++pf) {
        int p0 = 8 * pf + (lane & 3) * 2;
        *(float2*)(yr0 + p0) = make_float2(yacc[pf][0], yacc[pf][1]);
        *(float2*)(yr1 + p0) = make_float2(yacc[pf][2], yacc[pf][3]);
    }
}

// ---------------------------------------------------------------------------
extern "C" void kernel_launch(void* const* d_in, const int* in_sizes, int n_in,
                              void* d_out, int out_size) {
    const float* xg  = (const float*)d_in[0];
    const float* Ag  = (const float*)d_in[1];
    const float* Bg  = (const float*)d_in[2];
    const float* Cg  = (const float*)d_in[3];
    const float* Lm  = (const float*)d_in[4];
    const float* msf = (const float*)d_in[5];
    float* out = (float*)d_out;

    acs_kernel<<<BH, 1024>>>(Ag);
    conv_b_kernel<<<8192, 256>>>(Bg);
    conv_x_kernel<<<dim3(16, BH), 256>>>(xg);

    cudaFuncSetAttribute(ssd_mma_kernel,
                         cudaFuncAttributeMaxDynamicSharedMemorySize, SMEM_BYTES);
    ssd_mma_kernel<<<dim3(8, BH), THREADS, SMEM_BYTES>>>(Cg, Lm, msf, out);

    cudaFuncSetAttribute(fs_kernel,
                         cudaFuncAttributeMaxDynamicSharedMemorySize, FS_SMEM);
    fs_kernel<<<BH, 256, FS_SMEM>>>(out);
}